// round 1
// baseline (speedup 1.0000x reference)
#include <cuda_runtime.h>
#include <cstdint>
#include <cstddef>

#define MEMN 262144
#define BQ   128
#define DIM  512
#define TOPK 256

#define TM 64
#define TK 32

// ---------------- scratch (static __device__, no runtime alloc) ----------------
__device__ float g_qnT[DIM * BQ];                       // normalized query, transposed [k][b]
__device__ float g_scores[(size_t)BQ * MEMN];           // [b][m] cosine scores (134 MB)
__device__ int   g_topk_idx[BQ * TOPK];                 // selected indices for gather

// output layout: feat [B,K,D] | score [B,K] | index [B,K]  (all float32)
#define OFF_SCORE ((size_t)BQ * TOPK * DIM)
#define OFF_INDEX (OFF_SCORE + (size_t)BQ * TOPK)

// ---------------- key transforms: monotonic float<->uint ----------------
__device__ __forceinline__ unsigned fkey(float f) {
    unsigned u = __float_as_uint(f);
    return (u & 0x80000000u) ? ~u : (u | 0x80000000u);
}
__device__ __forceinline__ float unkey(unsigned k) {
    unsigned u = (k & 0x80000000u) ? (k ^ 0x80000000u) : ~k;
    return __uint_as_float(u);
}

// ---------------- kernel 1: L2-normalize query rows, store transposed ----------------
__global__ void k_norm(const float* __restrict__ q) {
    int b = blockIdx.x;
    __shared__ float red[32];
    float s = 0.f;
    for (int i = threadIdx.x; i < DIM; i += blockDim.x) {
        float v = q[b * DIM + i];
        s += v * v;
    }
    for (int o = 16; o; o >>= 1) s += __shfl_xor_sync(0xFFFFFFFFu, s, o);
    if ((threadIdx.x & 31) == 0) red[threadIdx.x >> 5] = s;
    __syncthreads();
    if (threadIdx.x < 32) {
        float v = (threadIdx.x < (blockDim.x >> 5)) ? red[threadIdx.x] : 0.f;
        for (int o = 16; o; o >>= 1) v += __shfl_xor_sync(0xFFFFFFFFu, v, o);
        if (threadIdx.x == 0) red[0] = v;
    }
    __syncthreads();
    float inv = 1.0f / sqrtf(red[0]);
    for (int i = threadIdx.x; i < DIM; i += blockDim.x)
        g_qnT[i * BQ + b] = q[b * DIM + i] * inv;
}

// ---------------- kernel 2: fp32 GEMM  scores[b][m] = sum_k qnT[k][b]*SK[m][k] ----------------
__global__ void __launch_bounds__(256, 2) k_gemm(const float* __restrict__ sk) {
    __shared__ float sA[TM][TK + 1];   // spatial_key tile [m][k], padded
    __shared__ float sQ[TK][BQ];       // query tile [k][b]
    int m0  = blockIdx.x * TM;
    int tid = threadIdx.x;
    int ty  = tid >> 4;    // 0..15 -> 4 m-rows each
    int tx  = tid & 15;    // 0..15 -> 8 b-cols each

    float acc[4][8];
#pragma unroll
    for (int i = 0; i < 4; i++)
#pragma unroll
        for (int j = 0; j < 8; j++) acc[i][j] = 0.f;

    for (int k0 = 0; k0 < DIM; k0 += TK) {
        // load SK tile: 64x32 floats, coalesced (32-float rows)
#pragma unroll
        for (int it = 0; it < 8; it++) {
            int idx = tid + it * 256;
            int r = idx >> 5, c = idx & 31;
            sA[r][c] = sk[(size_t)(m0 + r) * DIM + (k0 + c)];
        }
        // load Q tile: 32x128 floats, coalesced from transposed qnT
#pragma unroll
        for (int it = 0; it < 16; it++) {
            int idx = tid + it * 256;
            int kk = idx >> 7, bb = idx & 127;
            sQ[kk][bb] = g_qnT[(k0 + kk) * BQ + bb];
        }
        __syncthreads();
#pragma unroll
        for (int k = 0; k < TK; k++) {
            float a[4], qv[8];
#pragma unroll
            for (int i = 0; i < 4; i++) a[i] = sA[ty * 4 + i][k];
#pragma unroll
            for (int j = 0; j < 8; j++) qv[j] = sQ[k][tx * 8 + j];
#pragma unroll
            for (int i = 0; i < 4; i++)
#pragma unroll
                for (int j = 0; j < 8; j++) acc[i][j] = fmaf(a[i], qv[j], acc[i][j]);
        }
        __syncthreads();
    }
    // write back: 4 consecutive m per (thread,j) -> float4 stores
#pragma unroll
    for (int j = 0; j < 8; j++) {
        int b = tx * 8 + j;
        float4 v = make_float4(acc[0][j], acc[1][j], acc[2][j], acc[3][j]);
        *(float4*)(&g_scores[(size_t)b * MEMN + m0 + ty * 4]) = v;
    }
}

// ---------------- kernel 3: exact top-256 per row (radix select + bitonic sort) ----------------
__global__ void __launch_bounds__(1024) k_topk(float* __restrict__ out) {
    int b = blockIdx.x;
    const float* row = g_scores + (size_t)b * MEMN;

    __shared__ unsigned hist[256];
    __shared__ unsigned s_prefix, s_krem;
    __shared__ unsigned s_keys[TOPK];
    __shared__ int      s_idx[TOPK];
    __shared__ int      s_eq[1024];
    __shared__ int      s_ngt, s_neq;
    __shared__ unsigned long long s_c[TOPK];

    unsigned prefix = 0, pmask = 0;
    int krem = TOPK;

    // 4-pass MSB radix select: find exact threshold key T
    for (int shift = 24; shift >= 0; shift -= 8) {
        if (threadIdx.x < 256) hist[threadIdx.x] = 0;
        __syncthreads();
        for (int i = threadIdx.x; i < MEMN; i += 1024) {
            unsigned key = fkey(row[i]);
            if ((key & pmask) == prefix) atomicAdd(&hist[(key >> shift) & 255], 1u);
        }
        __syncthreads();
        if (threadIdx.x == 0) {
            unsigned cum = 0;
            int d = 255;
            for (; d > 0; d--) {
                unsigned c = hist[d];
                if (cum + c >= (unsigned)krem) break;
                cum += c;
            }
            s_prefix = prefix | ((unsigned)d << shift);
            s_krem   = (unsigned)krem - cum;
        }
        __syncthreads();
        prefix = s_prefix;
        krem   = (int)s_krem;
        pmask |= (0xFFu << shift);
        __syncthreads();
    }
    unsigned T = prefix;  // threshold key; take all >T, plus krem ties at T (smallest indices)

    if (threadIdx.x == 0) { s_ngt = 0; s_neq = 0; }
    __syncthreads();
    for (int i = threadIdx.x; i < MEMN; i += 1024) {
        unsigned key = fkey(row[i]);
        if (key > T) {
            int p = atomicAdd(&s_ngt, 1);
            if (p < TOPK) { s_keys[p] = key; s_idx[p] = i; }
        } else if (key == T) {
            int p = atomicAdd(&s_neq, 1);
            if (p < 1024) s_eq[p] = i;
        }
    }
    __syncthreads();

    int ngt = s_ngt;                       // == TOPK - krem
    int neq = s_neq < 1024 ? s_neq : 1024;

    // sort tie indices ascending (odd-even transposition; typically neq == krem == 1)
    for (int r = 0; r < neq; r++) {
        int i = (r & 1) + 2 * threadIdx.x;
        if (i + 1 < neq) {
            int a = s_eq[i], c = s_eq[i + 1];
            if (a > c) { s_eq[i] = c; s_eq[i + 1] = a; }
        }
        __syncthreads();
    }
    if (threadIdx.x < (unsigned)krem) {
        s_keys[ngt + threadIdx.x] = T;
        s_idx[ngt + threadIdx.x]  = s_eq[threadIdx.x];
    }
    __syncthreads();

    // composite sort key: score descending, index ascending
    if (threadIdx.x < TOPK)
        s_c[threadIdx.x] = ((unsigned long long)(~s_keys[threadIdx.x]) << 32) |
                           (unsigned)s_idx[threadIdx.x];
    __syncthreads();
    for (int ks = 2; ks <= TOPK; ks <<= 1) {
        for (int j = ks >> 1; j > 0; j >>= 1) {
            int i = threadIdx.x;
            if (i < TOPK) {
                int ixj = i ^ j;
                if (ixj > i) {
                    bool up = ((i & ks) == 0);
                    unsigned long long a = s_c[i], c = s_c[ixj];
                    if ((a > c) == up) { s_c[i] = c; s_c[ixj] = a; }
                }
            }
            __syncthreads();
        }
    }

    if (threadIdx.x < TOPK) {
        unsigned long long cc = s_c[threadIdx.x];
        unsigned key = ~(unsigned)(cc >> 32);
        int idx      = (int)(unsigned)(cc & 0xFFFFFFFFu);
        out[OFF_SCORE + (size_t)b * TOPK + threadIdx.x] = unkey(key);
        out[OFF_INDEX + (size_t)b * TOPK + threadIdx.x] = (float)idx;
        g_topk_idx[b * TOPK + threadIdx.x] = idx;
    }
}

// ---------------- kernel 4: gather color_value rows -> feat output ----------------
__global__ void k_gather(const float* __restrict__ cv, float* __restrict__ out) {
    int rowid = blockIdx.x;               // b*TOPK + j
    int idx   = g_topk_idx[rowid];
    const float4* src = (const float4*)(cv + (size_t)idx * DIM);
    float4*       dst = (float4*)(out + (size_t)rowid * DIM);
    dst[threadIdx.x] = src[threadIdx.x];  // 128 threads x float4 = 512 floats
}

// ---------------- launch ----------------
extern "C" void kernel_launch(void* const* d_in, const int* in_sizes, int n_in,
                              void* d_out, int out_size) {
    const float* q  = (const float*)d_in[0];
    const float* sk = (const float*)d_in[1];
    const float* cv = (const float*)d_in[2];
    float* out = (float*)d_out;

    k_norm<<<BQ, 256>>>(q);
    k_gemm<<<MEMN / TM, 256>>>(sk);
    k_topk<<<BQ, 1024>>>(out);
    k_gather<<<BQ * TOPK, 128>>>(cv, out);
}

// round 6
// speedup vs baseline: 2.7262x; 2.7262x over previous
#include <cuda_runtime.h>
#include <cstdint>
#include <cstddef>

#define MEMN 262144
#define BQ   128
#define DIM  512
#define TOPK 256

// ================= scratch (static __device__, no runtime alloc) =================
__device__ float g_qn[BQ * DIM];                         // normalized query fp32 [b][k]
__device__ float g_scores[(size_t)BQ * MEMN];            // [b][m] approx scores (134 MB)
#define SEG    16384
#define NPART  (MEMN / SEG)                              // 16
#define SEGK   512                                       // per-segment approx top-512
#define NCAND  (NPART * SEGK)                            // 8192 per row
#define RANKT  384                                       // approx-rank threshold for rescue
#define RESCAP 512                                       // rescore capacity
__device__ unsigned long long g_cand[(size_t)BQ * NCAND];  // 8 MB
__device__ int g_topk_idx[BQ * TOPK];

// output layout: feat [B,K,D] | score [B,K] | index [B,K]  (all float32)
#define OFF_SCORE ((size_t)BQ * TOPK * DIM)
#define OFF_INDEX (OFF_SCORE + (size_t)BQ * TOPK)

// ================= helpers =================
__device__ __forceinline__ unsigned fkey(float f) {
    unsigned u = __float_as_uint(f);
    return (u & 0x80000000u) ? ~u : (u | 0x80000000u);
}
__device__ __forceinline__ float unkey(unsigned k) {
    unsigned u = (k & 0x80000000u) ? (k ^ 0x80000000u) : ~k;
    return __uint_as_float(u);
}
__device__ __forceinline__ unsigned f2tf32(float x) {
    unsigned u;
    asm("cvt.rna.tf32.f32 %0, %1;" : "=r"(u) : "f"(x));
    return u;
}
__device__ __forceinline__ void mma8(float* d, const unsigned* a, const unsigned* b) {
    asm volatile(
        "mma.sync.aligned.m16n8k8.row.col.f32.tf32.tf32.f32 "
        "{%0,%1,%2,%3}, {%4,%5,%6,%7}, {%8,%9}, {%0,%1,%2,%3};"
        : "+f"(d[0]), "+f"(d[1]), "+f"(d[2]), "+f"(d[3])
        : "r"(a[0]), "r"(a[1]), "r"(a[2]), "r"(a[3]), "r"(b[0]), "r"(b[1]));
}

// ================= kernel 1: L2-normalize query rows =================
__global__ void k_norm(const float* __restrict__ q) {
    int b = blockIdx.x;
    __shared__ float red[32];
    float s = 0.f;
    for (int i = threadIdx.x; i < DIM; i += blockDim.x) {
        float v = q[b * DIM + i];
        s += v * v;
    }
    for (int o = 16; o; o >>= 1) s += __shfl_xor_sync(0xFFFFFFFFu, s, o);
    if ((threadIdx.x & 31) == 0) red[threadIdx.x >> 5] = s;
    __syncthreads();
    if (threadIdx.x < 32) {
        float v = (threadIdx.x < (blockDim.x >> 5)) ? red[threadIdx.x] : 0.f;
        for (int o = 16; o; o >>= 1) v += __shfl_xor_sync(0xFFFFFFFFu, v, o);
        if (threadIdx.x == 0) red[0] = v;
    }
    __syncthreads();
    float inv = 1.0f / sqrtf(red[0]);
    for (int i = threadIdx.x; i < DIM; i += blockDim.x)
        g_qn[b * DIM + i] = q[b * DIM + i] * inv;
}

// ================= kernel 2: single-pass TF32 approx GEMM =================
#define KC  32
#define NCHUNK (DIM / KC)      // 16
#define ST  36                 // row stride in floats
#define ARR (128 * ST)         // 4608
#define STG1 (2 * ARR)         // per stage: A | B
#define GEMM_SMEM (2 * STG1 * 4)  // 73728 bytes

__global__ void __launch_bounds__(256, 1) k_gemm(const float* __restrict__ sk) {
    extern __shared__ unsigned smu[];
    int tid  = threadIdx.x;
    int wid  = tid >> 5;
    int lane = tid & 31;
    int g = lane >> 2, t = lane & 3;
    int warpM = (wid & 1) * 64;
    int warpN = (wid >> 1) * 32;
    int m0 = blockIdx.x * 128;

    float acc[4][4][4];
#pragma unroll
    for (int i = 0; i < 4; i++)
#pragma unroll
        for (int j = 0; j < 4; j++)
#pragma unroll
            for (int e = 0; e < 4; e++) acc[i][j][e] = 0.f;

    float4 skv[4], qv[4];

    auto store_tile = [&](int st) {
#pragma unroll
        for (int it = 0; it < 4; it++) {
            int idx = tid + it * 256;
            int r = idx >> 3, c = idx & 7;
            unsigned* AH = smu + st * STG1;
            unsigned* BH = AH + ARR;
            uint4 h;
            h.x = f2tf32(skv[it].x); h.y = f2tf32(skv[it].y);
            h.z = f2tf32(skv[it].z); h.w = f2tf32(skv[it].w);
            *(uint4*)(AH + r * ST + 4 * c) = h;
            h.x = f2tf32(qv[it].x); h.y = f2tf32(qv[it].y);
            h.z = f2tf32(qv[it].z); h.w = f2tf32(qv[it].w);
            *(uint4*)(BH + r * ST + 4 * c) = h;
        }
    };
    auto load_gmem = [&](int ch) {
#pragma unroll
        for (int it = 0; it < 4; it++) {
            int idx = tid + it * 256;
            int r = idx >> 3, c = idx & 7;
            skv[it] = __ldg((const float4*)(sk + (size_t)(m0 + r) * DIM + ch * KC) + c);
            qv[it]  = __ldg((const float4*)(g_qn + (size_t)r * DIM + ch * KC) + c);
        }
    };

    load_gmem(0);
    store_tile(0);
    __syncthreads();

    for (int ch = 0; ch < NCHUNK; ch++) {
        int st = ch & 1;
        if (ch + 1 < NCHUNK) load_gmem(ch + 1);

        const unsigned* AH = smu + st * STG1;
        const unsigned* BH = AH + ARR;
#pragma unroll
        for (int s = 0; s < 4; s++) {
            int k0 = 8 * s + t;
            unsigned ah[4][4];
#pragma unroll
            for (int i = 0; i < 4; i++) {
                int r = warpM + 16 * i + g;
                ah[i][0] = AH[r * ST + k0];       ah[i][1] = AH[(r + 8) * ST + k0];
                ah[i][2] = AH[r * ST + k0 + 4];   ah[i][3] = AH[(r + 8) * ST + k0 + 4];
            }
            unsigned bh[4][2];
#pragma unroll
            for (int j = 0; j < 4; j++) {
                int n = warpN + 8 * j + g;
                bh[j][0] = BH[n * ST + k0];  bh[j][1] = BH[n * ST + k0 + 4];
            }
#pragma unroll
            for (int i = 0; i < 4; i++)
#pragma unroll
                for (int j = 0; j < 4; j++)
                    mma8(acc[i][j], ah[i], bh[j]);
        }
        if (ch + 1 < NCHUNK) {
            __syncthreads();
            store_tile((ch + 1) & 1);
            __syncthreads();
        }
    }

#pragma unroll
    for (int i = 0; i < 4; i++) {
        int m_lo = m0 + warpM + 16 * i + g;
#pragma unroll
        for (int j = 0; j < 4; j++) {
            int b0 = warpN + 8 * j + 2 * t;
            g_scores[(size_t)b0 * MEMN + m_lo]           = acc[i][j][0];
            g_scores[(size_t)(b0 + 1) * MEMN + m_lo]     = acc[i][j][1];
            g_scores[(size_t)b0 * MEMN + m_lo + 8]       = acc[i][j][2];
            g_scores[(size_t)(b0 + 1) * MEMN + m_lo + 8] = acc[i][j][3];
        }
    }
}

// ================= kernel 3: per-segment approx top-512 =================
__global__ void __launch_bounds__(512) k_part() {
    extern __shared__ unsigned skey[];   // SEG u32 = 64KB
    int p = blockIdx.x, b = blockIdx.y;
    const float* row = g_scores + (size_t)b * MEMN + (size_t)p * SEG;

    __shared__ unsigned hist[256];
    __shared__ unsigned s_prefix, s_krem;
    __shared__ unsigned ckey[SEGK];
    __shared__ int      cidx[SEGK];
    __shared__ int      s_eq[SEGK];
    __shared__ int      s_ngt, s_neq;

    for (int i = threadIdx.x; i < SEG; i += 512) skey[i] = fkey(row[i]);
    __syncthreads();

    unsigned prefix = 0, pmask = 0;
    int krem = SEGK;
    for (int shift = 24; shift >= 0; shift -= 8) {
        if (threadIdx.x < 256) hist[threadIdx.x] = 0;
        __syncthreads();
        for (int i = threadIdx.x; i < SEG; i += 512) {
            unsigned k = skey[i];
            if ((k & pmask) == prefix) atomicAdd(&hist[(k >> shift) & 255], 1u);
        }
        __syncthreads();
        if (threadIdx.x == 0) {
            unsigned cum = 0;
            int d = 255;
            for (; d > 0; d--) {
                unsigned c = hist[d];
                if (cum + c >= (unsigned)krem) break;
                cum += c;
            }
            s_prefix = prefix | ((unsigned)d << shift);
            s_krem   = (unsigned)krem - cum;
        }
        __syncthreads();
        prefix = s_prefix;
        krem   = (int)s_krem;
        pmask |= (0xFFu << shift);
        __syncthreads();
    }
    unsigned T = prefix;

    if (threadIdx.x == 0) { s_ngt = 0; s_neq = 0; }
    __syncthreads();
    for (int i = threadIdx.x; i < SEG; i += 512) {
        unsigned k = skey[i];
        if (k > T) {
            int pos = atomicAdd(&s_ngt, 1);
            if (pos < SEGK) { ckey[pos] = k; cidx[pos] = i; }
        } else if (k == T) {
            int pos = atomicAdd(&s_neq, 1);
            if (pos < SEGK) s_eq[pos] = i;
        }
    }
    __syncthreads();

    int ngt = s_ngt;                       // == SEGK - krem
    int neq = s_neq < SEGK ? s_neq : SEGK;
    for (int r = 0; r < neq; r++) {
        int i = (r & 1) + 2 * threadIdx.x;
        if (i + 1 < neq) {
            int a = s_eq[i], c = s_eq[i + 1];
            if (a > c) { s_eq[i] = c; s_eq[i + 1] = a; }
        }
        __syncthreads();
    }
    if (threadIdx.x < (unsigned)krem) {
        ckey[ngt + threadIdx.x] = T;
        cidx[ngt + threadIdx.x] = s_eq[threadIdx.x];
    }
    __syncthreads();

    if (threadIdx.x < SEGK) {
        unsigned gi = (unsigned)(p * SEG + cidx[threadIdx.x]);
        g_cand[((size_t)b * NPART + p) * SEGK + threadIdx.x] =
            ((unsigned long long)ckey[threadIdx.x] << 32) | (0xFFFFFFFFu - gi);
    }
}

// ================= kernel 4: select + exact rescore + final sort =================
// smem: cand[8192] u64 (64KB) | qs[512] f32 (2KB) | ex[512] u64 (4KB)
#define SEL_SMEM (NCAND * 8 + DIM * 4 + RESCAP * 8)

__global__ void __launch_bounds__(1024) k_select(const float* __restrict__ sk,
                                                 float* __restrict__ out) {
    extern __shared__ char sm[];
    unsigned long long* cand = (unsigned long long*)sm;
    float* qs = (float*)(sm + NCAND * 8);
    unsigned long long* ex = (unsigned long long*)(sm + NCAND * 8 + DIM * 4);
    int b = blockIdx.x;
    int tid = threadIdx.x;

    __shared__ unsigned hist[256];
    __shared__ unsigned s_prefix, s_krem;
    __shared__ int s_cnt;

    for (int i = tid; i < NCAND; i += 1024) cand[i] = g_cand[(size_t)b * NCAND + i];
    for (int i = tid; i < DIM; i += 1024) qs[i] = g_qn[b * DIM + i];
    if (tid < RESCAP) ex[tid] = 0ull;
    if (tid == 0) s_cnt = 0;
    __syncthreads();

    // radix-select approx rank-RANKT threshold T over candidate hi-keys
    unsigned prefix = 0, pmask = 0;
    int krem = RANKT;
    for (int shift = 24; shift >= 0; shift -= 8) {
        if (tid < 256) hist[tid] = 0;
        __syncthreads();
        for (int i = tid; i < NCAND; i += 1024) {
            unsigned k = (unsigned)(cand[i] >> 32);
            if ((k & pmask) == prefix) atomicAdd(&hist[(k >> shift) & 255], 1u);
        }
        __syncthreads();
        if (tid == 0) {
            unsigned cum = 0;
            int d = 255;
            for (; d > 0; d--) {
                unsigned c = hist[d];
                if (cum + c >= (unsigned)krem) break;
                cum += c;
            }
            s_prefix = prefix | ((unsigned)d << shift);
            s_krem   = (unsigned)krem - cum;
        }
        __syncthreads();
        prefix = s_prefix;
        krem   = (int)s_krem;
        pmask |= (0xFFu << shift);
        __syncthreads();
    }
    unsigned T = prefix;

    // collect all candidates with approx key >= T (set deterministic; >=RANKT, <=RESCAP)
    for (int i = tid; i < NCAND; i += 1024) {
        unsigned k = (unsigned)(cand[i] >> 32);
        if (k >= T) {
            int pos = atomicAdd(&s_cnt, 1);
            if (pos < RESCAP) ex[pos] = cand[i];
        }
    }
    __syncthreads();

    // exact rescore: sequential ascending-k fp32 fmaf chain (reference-compatible)
    if (tid < RESCAP) {
        unsigned long long c = ex[tid];
        if (c != 0ull) {
            int m = (int)(0xFFFFFFFFu - (unsigned)(c & 0xFFFFFFFFu));
            const float4* r4 = (const float4*)(sk + (size_t)m * DIM);
            float acc = 0.f;
#pragma unroll 16
            for (int cc = 0; cc < DIM / 4; cc++) {
                float4 v = __ldg(r4 + cc);
                acc = fmaf(v.x, qs[4 * cc + 0], acc);
                acc = fmaf(v.y, qs[4 * cc + 1], acc);
                acc = fmaf(v.z, qs[4 * cc + 2], acc);
                acc = fmaf(v.w, qs[4 * cc + 3], acc);
            }
            ex[tid] = ((unsigned long long)fkey(acc) << 32) | (0xFFFFFFFFu - (unsigned)m);
        }
    }
    __syncthreads();

    // bitonic sort RESCAP=512 descending by exact composite
    for (int k = 2; k <= RESCAP; k <<= 1) {
        for (int j = k >> 1; j > 0; j >>= 1) {
            if (tid < RESCAP) {
                int i = tid, ixj = i ^ j;
                if (ixj > i) {
                    bool desc = ((i & k) == 0);
                    unsigned long long a = ex[i], c = ex[ixj];
                    if (desc ? (a < c) : (a > c)) { ex[i] = c; ex[ixj] = a; }
                }
            }
            __syncthreads();
        }
    }

    if (tid < TOPK) {
        unsigned long long c = ex[tid];
        unsigned key = (unsigned)(c >> 32);
        unsigned idx = 0xFFFFFFFFu - (unsigned)(c & 0xFFFFFFFFu);
        out[OFF_SCORE + (size_t)b * TOPK + tid] = unkey(key);
        out[OFF_INDEX + (size_t)b * TOPK + tid] = (float)idx;
        g_topk_idx[b * TOPK + tid] = (int)idx;
    }
}

// ================= kernel 5: gather =================
__global__ void k_gather(const float* __restrict__ cv, float* __restrict__ out) {
    int rowid = blockIdx.x;
    int idx   = g_topk_idx[rowid];
    const float4* src = (const float4*)(cv + (size_t)idx * DIM);
    float4*       dst = (float4*)(out + (size_t)rowid * DIM);
    dst[threadIdx.x] = src[threadIdx.x];
}

// ================= launch =================
extern "C" void kernel_launch(void* const* d_in, const int* in_sizes, int n_in,
                              void* d_out, int out_size) {
    const float* q  = (const float*)d_in[0];
    const float* sk = (const float*)d_in[1];
    const float* cv = (const float*)d_in[2];
    float* out = (float*)d_out;

    cudaFuncSetAttribute(k_gemm,   cudaFuncAttributeMaxDynamicSharedMemorySize, GEMM_SMEM);
    cudaFuncSetAttribute(k_part,   cudaFuncAttributeMaxDynamicSharedMemorySize, SEG * 4);
    cudaFuncSetAttribute(k_select, cudaFuncAttributeMaxDynamicSharedMemorySize, SEL_SMEM);

    k_norm<<<BQ, 256>>>(q);
    k_gemm<<<MEMN / 128, 256, GEMM_SMEM>>>(sk);
    k_part<<<dim3(NPART, BQ), 512, SEG * 4>>>();
    k_select<<<BQ, 1024, SEL_SMEM>>>(sk, out);
    k_gather<<<BQ * TOPK, 128>>>(cv, out);
}